// round 2
// baseline (speedup 1.0000x reference)
#include <cuda_runtime.h>
#include <math.h>

// Problem constants
// B=16, S=128, N=64, E=DK=H=128, L=32

// -------- device scratch (allocation-free rule: __device__ globals) --------
__device__ float g_Xg[2*16*128*512];   // precomputed X@Wcx+bc per dir (scan-time order)
__device__ float g_Xl[2*16*128*128];   // X@Wlx+bl
__device__ float g_Wg[2*16*64*384];    // Xw@Wwx+bw
__device__ float g_feats[16*128*256];  // concat(fwd,bwd) hidden features
__device__ float g_logits[16*128*32];
__device__ float g_res[16];

__device__ __forceinline__ float sigm(float x) { return 1.f / (1.f + expf(-x)); }

// ---------------- precompute GEMMs with embedding gather ----------------
// out[r, c] = sum_k emb[id(r)][k] * W_dir[k][c] + bias_dir[c]
// mode 0: Xg (C=512), mode 1: Xl (C=128) rows = dir*2048 + b*128 + t (t in scan order)
// mode 2: Wg (C=384) rows = dir*1024 + b*64 + w
__global__ void gemm_gather_kernel(int mode,
    const int* __restrict__ char_ids, const int* __restrict__ kb_ids,
    const float* __restrict__ char_emb, const float* __restrict__ kb_emb,
    const float* __restrict__ Wf, const float* __restrict__ Wr,
    const float* __restrict__ bf, const float* __restrict__ br,
    int C, int rows_per_dir)
{
    __shared__ float As[64 * 128];
    __shared__ float Ws[32 * 64];
    __shared__ int ids[64];
    int tid = threadIdx.x;
    int c0 = blockIdx.x * 64;
    int r0 = blockIdx.y * 64;
    int dir = (r0 >= rows_per_dir) ? 1 : 0;

    float* out = (mode == 0) ? g_Xg : (mode == 1) ? g_Xl : g_Wg;
    const float* emb = (mode == 2) ? kb_emb : char_emb;

    if (tid < 64) {
        int r = r0 + tid;
        int id;
        if (mode < 2) {
            int t = r & 127, b = (r >> 7) & 15;
            int pos = dir ? (127 - t) : t;   // bwd scans reversed chars
            id = char_ids[b * 128 + pos];
        } else {
            int w = r & 63, b = (r >> 6) & 15;
            id = kb_ids[b * 64 + w];
        }
        ids[tid] = id;
    }
    __syncthreads();
    // gather A tile: 64 rows x 128 K
    for (int i = tid; i < 64 * 32; i += 256) {
        int row = i >> 5, q = i & 31;
        float4 v = reinterpret_cast<const float4*>(emb + (size_t)ids[row] * 128)[q];
        reinterpret_cast<float4*>(As + row * 128)[q] = v;
    }

    const float* W = dir ? Wr : Wf;
    const float* bias = dir ? br : bf;
    int tx = tid & 15, ty = tid >> 4;
    float acc[4][4] = {};

    for (int kc = 0; kc < 4; ++kc) {
        __syncthreads();
        for (int i = tid; i < 2048; i += 256) {
            int kk = i >> 6, cc = i & 63;
            Ws[i] = W[(size_t)(kc * 32 + kk) * C + c0 + cc];
        }
        __syncthreads();
        #pragma unroll 8
        for (int kk = 0; kk < 32; ++kk) {
            float a0 = As[(ty * 4 + 0) * 128 + kc * 32 + kk];
            float a1 = As[(ty * 4 + 1) * 128 + kc * 32 + kk];
            float a2 = As[(ty * 4 + 2) * 128 + kc * 32 + kk];
            float a3 = As[(ty * 4 + 3) * 128 + kc * 32 + kk];
            float w0 = Ws[kk * 64 + tx * 4 + 0];
            float w1 = Ws[kk * 64 + tx * 4 + 1];
            float w2 = Ws[kk * 64 + tx * 4 + 2];
            float w3 = Ws[kk * 64 + tx * 4 + 3];
            acc[0][0] = fmaf(a0, w0, acc[0][0]); acc[0][1] = fmaf(a0, w1, acc[0][1]);
            acc[0][2] = fmaf(a0, w2, acc[0][2]); acc[0][3] = fmaf(a0, w3, acc[0][3]);
            acc[1][0] = fmaf(a1, w0, acc[1][0]); acc[1][1] = fmaf(a1, w1, acc[1][1]);
            acc[1][2] = fmaf(a1, w2, acc[1][2]); acc[1][3] = fmaf(a1, w3, acc[1][3]);
            acc[2][0] = fmaf(a2, w0, acc[2][0]); acc[2][1] = fmaf(a2, w1, acc[2][1]);
            acc[2][2] = fmaf(a2, w2, acc[2][2]); acc[2][3] = fmaf(a2, w3, acc[2][3]);
            acc[3][0] = fmaf(a3, w0, acc[3][0]); acc[3][1] = fmaf(a3, w1, acc[3][1]);
            acc[3][2] = fmaf(a3, w2, acc[3][2]); acc[3][3] = fmaf(a3, w3, acc[3][3]);
        }
    }
    #pragma unroll
    for (int i = 0; i < 4; ++i) {
        int r = r0 + ty * 4 + i;
        #pragma unroll
        for (int j = 0; j < 4; ++j) {
            int c = c0 + tx * 4 + j;
            out[(size_t)r * C + c] = acc[i][j] + bias[c];
        }
    }
}

// ---------------- lattice LSTM scan: one block per (b, dir) ----------------
__global__ void lattice_kernel(
    const int* __restrict__ word_begin, const int* __restrict__ word_len,
    const int* __restrict__ seq_len,
    const float* __restrict__ f_Wch, const float* __restrict__ f_Wwh, const float* __restrict__ f_Wlc,
    const float* __restrict__ r_Wch, const float* __restrict__ r_Wwh, const float* __restrict__ r_Wlc)
{
    extern __shared__ float sm[];
    float* h_hist = sm;                       // 129*128
    float* c_hist = h_hist + 129 * 128;       // 129*128
    float* gates  = c_hist + 129 * 128;       // 512
    float* wvec   = gates + 512;              // 384
    float* cw_s   = wvec + 384;               // 128
    float* ew_sum = cw_s + 128;               // 128
    float* ewcw   = ew_sum + 128;             // 128
    __shared__ int s_wbeg[64];
    __shared__ int s_wend[64];
    __shared__ unsigned s_m0, s_m1;

    int tid = threadIdx.x;
    int blk = blockIdx.x;
    int dir = blk >> 4, b = blk & 15;
    const float* Wch = dir ? r_Wch : f_Wch;
    const float* Wwh = dir ? r_Wwh : f_Wwh;
    const float* Wlc = dir ? r_Wlc : f_Wlc;
    const float* Xg = g_Xg + (size_t)(dir * 16 + b) * 128 * 512;
    const float* Xl = g_Xl + (size_t)(dir * 16 + b) * 128 * 128;
    const float* Wg = g_Wg + (size_t)(dir * 16 + b) * 64 * 384;
    int L = seq_len[b];

    for (int i = tid; i < 129 * 128; i += 256) { h_hist[i] = 0.f; c_hist[i] = 0.f; }
    if (tid < 64) {
        int bg = word_begin[b * 64 + tid];
        int ln = word_len[b * 64 + tid];
        int e = min(bg + ln, 127);
        int valid = (e < L);
        int be, en;
        if (dir == 0) { be = bg; en = e; } else { be = 127 - e; en = 127 - bg; }
        s_wbeg[tid] = be;
        s_wend[tid] = valid ? en : -1;
    }
    __syncthreads();

    for (int t = 0; t < 128; ++t) {
        const float* h_prev = h_hist + t * 128;
        // ---- phase A: char-LSTM gates: 512 cols, 2 per thread ----
        {
            float2 acc = reinterpret_cast<const float2*>(Xg + (size_t)t * 512)[tid];
            const float2* Wp = reinterpret_cast<const float2*>(Wch) + tid;
            #pragma unroll 8
            for (int k = 0; k < 128; ++k) {
                float hk = h_prev[k];
                float2 w = Wp[(size_t)k * 256];
                acc.x = fmaf(hk, w.x, acc.x);
                acc.y = fmaf(hk, w.y, acc.y);
            }
            gates[2 * tid]     = acc.x;
            gates[2 * tid + 1] = acc.y;
        }
        if (tid < 128) { ew_sum[tid] = 0.f; ewcw[tid] = 0.f; }
        if (tid < 64) {
            unsigned m = __ballot_sync(0xffffffffu, s_wend[tid] == t);
            if ((tid & 31) == 0) { if (tid < 32) s_m0 = m; else s_m1 = m; }
        }
        __syncthreads();

        unsigned m0 = s_m0, m1 = s_m1;
        int wcnt = __popc(m0) + __popc(m1);
        // ---- phase B: words ending at t (deterministic ascending order) ----
        while (m0 | m1) {
            int w;
            if (m0) { w = __ffs(m0) - 1; m0 &= m0 - 1; }
            else    { w = 32 + __ffs(m1) - 1; m1 &= m1 - 1; }
            int bg = s_wbeg[w];
            const float* hb = h_hist + bg * 128;
            const float* cb = c_hist + bg * 128;
            if (tid < 192) {
                float2 acc = reinterpret_cast<const float2*>(Wg + (size_t)w * 384)[tid];
                const float2* Wp = reinterpret_cast<const float2*>(Wwh) + tid;
                #pragma unroll 8
                for (int k = 0; k < 128; ++k) {
                    float hk = hb[k];
                    float2 ww = Wp[(size_t)k * 192];
                    acc.x = fmaf(hk, ww.x, acc.x);
                    acc.y = fmaf(hk, ww.y, acc.y);
                }
                wvec[2 * tid]     = acc.x;
                wvec[2 * tid + 1] = acc.y;
            }
            __syncthreads();
            if (tid < 128) {
                float wi = sigm(wvec[tid]);
                float wf = sigm(wvec[128 + tid]);
                float wg = tanhf(wvec[256 + tid]);
                cw_s[tid] = wf * cb[tid] + wi * wg;
            }
            __syncthreads();
            if (tid < 64) {
                float2 acc = reinterpret_cast<const float2*>(Xl + (size_t)t * 128)[tid];
                const float2* Wp = reinterpret_cast<const float2*>(Wlc) + tid;
                #pragma unroll 8
                for (int k = 0; k < 128; ++k) {
                    float ck = cw_s[k];
                    float2 w2 = Wp[(size_t)k * 64];
                    acc.x = fmaf(ck, w2.x, acc.x);
                    acc.y = fmaf(ck, w2.y, acc.y);
                }
                int c = 2 * tid;
                float e0 = expf(sigm(acc.x));
                float e1 = expf(sigm(acc.y));
                ew_sum[c]     += e0; ewcw[c]     += e0 * cw_s[c];
                ew_sum[c + 1] += e1; ewcw[c + 1] += e1 * cw_s[c + 1];
            }
            __syncthreads();
        }
        // ---- phase C: combine, state update, feature output ----
        if (tid < 128) {
            float i_ = sigm(gates[tid]);
            float f_ = sigm(gates[128 + tid]);
            float o_ = sigm(gates[256 + tid]);
            float g_ = tanhf(gates[384 + tid]);
            float cp = c_hist[t * 128 + tid];
            float ct;
            if (wcnt > 0) {
                float ec = expf(i_);
                ct = (ec * g_ + ewcw[tid]) / (ec + ew_sum[tid]);
            } else {
                ct = f_ * cp + i_ * g_;
            }
            float ht = o_ * tanhf(ct);
            bool v = (dir == 0) ? (t < L) : (t >= 128 - L);
            h_hist[(t + 1) * 128 + tid] = v ? ht : h_prev[tid];
            c_hist[(t + 1) * 128 + tid] = v ? ct : cp;
            int pos = dir ? (127 - t) : t;
            g_feats[((size_t)b * 128 + pos) * 256 + dir * 128 + tid] = v ? ht : 0.f;
        }
        __syncthreads();
    }
}

// ---------------- dense projection ----------------
__global__ void dense_kernel(const float* __restrict__ W, const float* __restrict__ bias)
{
    int row = blockIdx.x;       // 0..2047 = b*128 + t
    int l = threadIdx.x;        // 0..31
    const float* f = g_feats + (size_t)row * 256;
    float acc = bias[l];
    #pragma unroll 8
    for (int j = 0; j < 256; ++j) acc = fmaf(f[j], W[j * 32 + l], acc);
    g_logits[(size_t)row * 32 + l] = acc;
}

// ---------------- CRF forward + gold score, one warp per batch ----------------
__global__ void crf_kernel(const int* __restrict__ label, const int* __restrict__ seq_len,
                           const float* __restrict__ crf_T)
{
    int b = blockIdx.x, l = threadIdx.x;
    __shared__ float Ts[1024];
    for (int i = l; i < 1024; i += 32) Ts[i] = crf_T[i];
    __syncwarp();
    int L = seq_len[b];
    const float* lg = g_logits + (size_t)b * 128 * 32;
    float alpha = lg[l];
    for (int t = 1; t < 128; ++t) {
        float v[32];
        float vmax = -1e30f;
        #pragma unroll
        for (int i = 0; i < 32; ++i) {
            float ai = __shfl_sync(0xffffffffu, alpha, i);
            v[i] = ai + Ts[i * 32 + l];
            vmax = fmaxf(vmax, v[i]);
        }
        float s = 0.f;
        #pragma unroll
        for (int i = 0; i < 32; ++i) s += expf(v[i] - vmax);
        float nv = vmax + logf(s) + lg[t * 32 + l];
        if (t < L) alpha = nv;      // mask[:,1:]: keep alpha where position invalid
    }
    // logZ = logsumexp(alpha)
    float m = alpha;
    for (int o = 16; o; o >>= 1) m = fmaxf(m, __shfl_xor_sync(0xffffffffu, m, o));
    float e = expf(alpha - m);
    for (int o = 16; o; o >>= 1) e += __shfl_xor_sync(0xffffffffu, e, o);
    float logZ = m + logf(e);
    // gold score
    float gsum = 0.f;
    for (int t = l; t < 128; t += 32) {
        if (t < L) {
            int lab = label[b * 128 + t];
            gsum += lg[t * 32 + lab];
            if (t >= 1) gsum += Ts[label[b * 128 + t - 1] * 32 + lab];
        }
    }
    for (int o = 16; o; o >>= 1) gsum += __shfl_xor_sync(0xffffffffu, gsum, o);
    if (l == 0) g_res[b] = logZ - gsum;
}

__global__ void finalize_kernel(float* out)
{
    float s = 0.f;
    #pragma unroll
    for (int b = 0; b < 16; ++b) s += g_res[b];
    out[0] = s * 0.0625f;   // mean over B=16
}

// ---------------- launch ----------------
extern "C" void kernel_launch(void* const* d_in, const int* in_sizes, int n_in,
                              void* d_out, int out_size)
{
    const int*   char_ids    = (const int*)d_in[0];
    const int*   kb_word_ids = (const int*)d_in[1];
    const int*   word_begin  = (const int*)d_in[2];
    const int*   word_len    = (const int*)d_in[3];
    const int*   label       = (const int*)d_in[4];
    const int*   seq_len     = (const int*)d_in[5];
    const float* char_emb    = (const float*)d_in[6];
    const float* kb_emb      = (const float*)d_in[7];
    const float* dense_W     = (const float*)d_in[8];
    const float* dense_b     = (const float*)d_in[9];
    const float* crf_T       = (const float*)d_in[10];
    const float* f_Wcx = (const float*)d_in[11];
    const float* f_Wch = (const float*)d_in[12];
    const float* f_bc  = (const float*)d_in[13];
    const float* f_Wwx = (const float*)d_in[14];
    const float* f_Wwh = (const float*)d_in[15];
    const float* f_bw  = (const float*)d_in[16];
    const float* f_Wlx = (const float*)d_in[17];
    const float* f_Wlc = (const float*)d_in[18];
    const float* f_bl  = (const float*)d_in[19];
    const float* r_Wcx = (const float*)d_in[20];
    const float* r_Wch = (const float*)d_in[21];
    const float* r_bc  = (const float*)d_in[22];
    const float* r_Wwx = (const float*)d_in[23];
    const float* r_Wwh = (const float*)d_in[24];
    const float* r_bw  = (const float*)d_in[25];
    const float* r_Wlx = (const float*)d_in[26];
    const float* r_Wlc = (const float*)d_in[27];
    const float* r_bl  = (const float*)d_in[28];

    const int LAT_SMEM = (129 * 128 * 2 + 512 + 384 + 128 * 3) * 4;  // 137216 B
    cudaFuncSetAttribute(lattice_kernel, cudaFuncAttributeMaxDynamicSharedMemorySize, LAT_SMEM);

    // precompute GEMMs
    gemm_gather_kernel<<<dim3(8, 64), 256>>>(0, char_ids, kb_word_ids, char_emb, kb_emb,
                                             f_Wcx, r_Wcx, f_bc, r_bc, 512, 2048);
    gemm_gather_kernel<<<dim3(2, 64), 256>>>(1, char_ids, kb_word_ids, char_emb, kb_emb,
                                             f_Wlx, r_Wlx, f_bl, r_bl, 128, 2048);
    gemm_gather_kernel<<<dim3(6, 32), 256>>>(2, char_ids, kb_word_ids, char_emb, kb_emb,
                                             f_Wwx, r_Wwx, f_bw, r_bw, 384, 1024);
    // lattice scan
    lattice_kernel<<<32, 256, LAT_SMEM>>>(word_begin, word_len, seq_len,
                                          f_Wch, f_Wwh, f_Wlc, r_Wch, r_Wwh, r_Wlc);
    // epilogue
    dense_kernel<<<2048, 32>>>(dense_W, dense_b);
    crf_kernel<<<16, 32>>>(label, seq_len, crf_T);
    finalize_kernel<<<1, 1>>>((float*)d_out);
}

// round 3
// speedup vs baseline: 3.7340x; 3.7340x over previous
#include <cuda_runtime.h>
#include <math.h>

// B=16, S=128, N=64, E=DK=H=128, L=32

// -------- device scratch --------
__device__ float g_Xg[2*16*128*512];   // X@Wcx+bc, scan order
__device__ float g_Xl[2*16*128*128];   // X@Wlx+bl
__device__ float g_Wg[2*16*64*384];    // Xw@Wwx+bw
__device__ float g_feats[16*128*256];
__device__ float g_logits[16*128*32];
__device__ float g_res[16];
__device__ float g_hh[128][129*128];   // per-CTA private history copies
__device__ float g_hc[128][129*128];

__device__ __forceinline__ float sigm(float x) { return 1.f / (1.f + expf(-x)); }

__device__ __forceinline__ unsigned smem_u32(const void* p) {
    unsigned a;
    asm("{ .reg .u64 t; cvta.to.shared.u64 t, %1; cvt.u32.u64 %0, t; }" : "=r"(a) : "l"(p));
    return a;
}
__device__ __forceinline__ void st_cluster_f32(unsigned local_addr, int peer, float v) {
    unsigned r;
    asm volatile("mapa.shared::cluster.u32 %0, %1, %2;" : "=r"(r) : "r"(local_addr), "r"(peer));
    asm volatile("st.shared::cluster.f32 [%0], %1;" :: "r"(r), "f"(v) : "memory");
}
__device__ __forceinline__ void cluster_sync_() {
    asm volatile("barrier.cluster.arrive.aligned;" ::: "memory");
    asm volatile("barrier.cluster.wait.aligned;" ::: "memory");
}

// ---------------- precompute GEMMs with embedding gather ----------------
__global__ void gemm_gather_kernel(int mode,
    const int* __restrict__ char_ids, const int* __restrict__ kb_ids,
    const float* __restrict__ char_emb, const float* __restrict__ kb_emb,
    const float* __restrict__ Wf, const float* __restrict__ Wr,
    const float* __restrict__ bf, const float* __restrict__ br,
    int C, int rows_per_dir)
{
    __shared__ float As[64 * 128];
    __shared__ float Ws[32 * 64];
    __shared__ int ids[64];
    int tid = threadIdx.x;
    int c0 = blockIdx.x * 64;
    int r0 = blockIdx.y * 64;
    int dir = (r0 >= rows_per_dir) ? 1 : 0;

    float* out = (mode == 0) ? g_Xg : (mode == 1) ? g_Xl : g_Wg;
    const float* emb = (mode == 2) ? kb_emb : char_emb;

    if (tid < 64) {
        int r = r0 + tid;
        int id;
        if (mode < 2) {
            int t = r & 127, b = (r >> 7) & 15;
            int pos = dir ? (127 - t) : t;
            id = char_ids[b * 128 + pos];
        } else {
            int w = r & 63, b = (r >> 6) & 15;
            id = kb_ids[b * 64 + w];
        }
        ids[tid] = id;
    }
    __syncthreads();
    for (int i = tid; i < 64 * 32; i += 256) {
        int row = i >> 5, q = i & 31;
        float4 v = reinterpret_cast<const float4*>(emb + (size_t)ids[row] * 128)[q];
        reinterpret_cast<float4*>(As + row * 128)[q] = v;
    }

    const float* W = dir ? Wr : Wf;
    const float* bias = dir ? br : bf;
    int tx = tid & 15, ty = tid >> 4;
    float acc[4][4] = {};

    for (int kc = 0; kc < 4; ++kc) {
        __syncthreads();
        for (int i = tid; i < 2048; i += 256) {
            int kk = i >> 6, cc = i & 63;
            Ws[i] = W[(size_t)(kc * 32 + kk) * C + c0 + cc];
        }
        __syncthreads();
        #pragma unroll 8
        for (int kk = 0; kk < 32; ++kk) {
            float a0 = As[(ty * 4 + 0) * 128 + kc * 32 + kk];
            float a1 = As[(ty * 4 + 1) * 128 + kc * 32 + kk];
            float a2 = As[(ty * 4 + 2) * 128 + kc * 32 + kk];
            float a3 = As[(ty * 4 + 3) * 128 + kc * 32 + kk];
            float w0 = Ws[kk * 64 + tx * 4 + 0];
            float w1 = Ws[kk * 64 + tx * 4 + 1];
            float w2 = Ws[kk * 64 + tx * 4 + 2];
            float w3 = Ws[kk * 64 + tx * 4 + 3];
            acc[0][0] = fmaf(a0, w0, acc[0][0]); acc[0][1] = fmaf(a0, w1, acc[0][1]);
            acc[0][2] = fmaf(a0, w2, acc[0][2]); acc[0][3] = fmaf(a0, w3, acc[0][3]);
            acc[1][0] = fmaf(a1, w0, acc[1][0]); acc[1][1] = fmaf(a1, w1, acc[1][1]);
            acc[1][2] = fmaf(a1, w2, acc[1][2]); acc[1][3] = fmaf(a1, w3, acc[1][3]);
            acc[2][0] = fmaf(a2, w0, acc[2][0]); acc[2][1] = fmaf(a2, w1, acc[2][1]);
            acc[2][2] = fmaf(a2, w2, acc[2][2]); acc[2][3] = fmaf(a2, w3, acc[2][3]);
            acc[3][0] = fmaf(a3, w0, acc[3][0]); acc[3][1] = fmaf(a3, w1, acc[3][1]);
            acc[3][2] = fmaf(a3, w2, acc[3][2]); acc[3][3] = fmaf(a3, w3, acc[3][3]);
        }
    }
    #pragma unroll
    for (int i = 0; i < 4; ++i) {
        int r = r0 + ty * 4 + i;
        #pragma unroll
        for (int j = 0; j < 4; ++j) {
            int c = c0 + tx * 4 + j;
            out[(size_t)r * C + c] = acc[i][j] + bias[c];
        }
    }
}

// ---------------- lattice scan: 4-CTA cluster per (b, dir), weights in smem ----------------
// smem layout (floats):
//   Ws  [128][128] quarter of Wch (this rank's gate)        @ 0      (16384)
//   Ww  [128][96]  slice of Wwh                             @ 16384  (12288)
//   Wl  [128][32]  slice of Wlc                             @ 28672  (4096)
//   gates [2][512] double-buffered full gate vector         @ 32768  (1024)
//   part  [256]                                             @ 33792
//   h_cur [128], c_cur [128]                                @ 34048, 34176
//   wvec [384]                                              @ 34304
//   lvec [128]                                              @ 34688
//   cw [128], ew [128], ewcw [128]                          @ 34816, 34944, 35072
//   hb_s [128], cb_s [128]                                  @ 35200, 35328
//   total 35456 floats = 141824 B
#define LAT_SMEM_FLOATS 35456

__global__ void __cluster_dims__(4, 1, 1) __launch_bounds__(256, 1)
lattice_kernel(
    const int* __restrict__ word_begin, const int* __restrict__ word_len,
    const int* __restrict__ seq_len,
    const float* __restrict__ f_Wch, const float* __restrict__ f_Wwh, const float* __restrict__ f_Wlc,
    const float* __restrict__ r_Wch, const float* __restrict__ r_Wwh, const float* __restrict__ r_Wlc)
{
    extern __shared__ float sm[];
    float* Ws    = sm;
    float* Ww    = sm + 16384;
    float* Wl    = sm + 28672;
    float* gates = sm + 32768;
    float* part  = sm + 33792;
    float* h_cur = sm + 34048;
    float* c_cur = sm + 34176;
    float* wvec  = sm + 34304;
    float* lvec  = sm + 34688;
    float* cw    = sm + 34816;
    float* ew    = sm + 34944;
    float* ewcw  = sm + 35072;
    float* hb_s  = sm + 35200;
    float* cb_s  = sm + 35328;
    __shared__ int s_wbeg[64];
    __shared__ int s_wend[64];
    __shared__ unsigned s_m0, s_m1;

    int tid  = threadIdx.x;
    int cta  = blockIdx.x;
    int sid  = cta >> 2;        // (b,dir) id
    int rank = cta & 3;         // cluster rank (blockIdx order == cluster rank order)
    int dir = sid >> 4, b = sid & 15;

    const float* Wch = dir ? r_Wch : f_Wch;
    const float* Wwh = dir ? r_Wwh : f_Wwh;
    const float* Wlc = dir ? r_Wlc : f_Wlc;
    const float* Xg  = g_Xg + (size_t)sid * 128 * 512;
    const float* Xl  = g_Xl + (size_t)sid * 128 * 128;
    const float* Wg  = g_Wg + (size_t)sid * 64 * 384;
    float* hh = g_hh[cta];
    float* hc = g_hc[cta];
    int L = seq_len[b];

    // load weight slices into smem
    for (int i = tid; i < 128 * 32; i += 256) {   // Wch quarter: cols [rank*128, +128)
        int row = i >> 5, q = i & 31;
        float4 v = reinterpret_cast<const float4*>(Wch + (size_t)row * 512 + rank * 128)[q];
        reinterpret_cast<float4*>(Ws + row * 128)[q] = v;
    }
    for (int i = tid; i < 128 * 24; i += 256) {   // Wwh slice: cols [rank*96, +96)
        int row = i / 24, q = i % 24;
        float4 v = reinterpret_cast<const float4*>(Wwh + (size_t)row * 384 + rank * 96)[q];
        reinterpret_cast<float4*>(Ww + row * 96)[q] = v;
    }
    for (int i = tid; i < 128 * 8; i += 256) {    // Wlc slice: cols [rank*32, +32)
        int row = i >> 3, q = i & 7;
        float4 v = reinterpret_cast<const float4*>(Wlc + (size_t)row * 128 + rank * 32)[q];
        reinterpret_cast<float4*>(Wl + row * 32)[q] = v;
    }
    if (tid < 128) {
        h_cur[tid] = 0.f; c_cur[tid] = 0.f;
        hh[tid] = 0.f;    hc[tid] = 0.f;
    }
    if (tid < 64) {
        int bg = word_begin[b * 64 + tid];
        int ln = word_len[b * 64 + tid];
        int e = min(bg + ln, 127);
        int valid = (e < L);
        int be, en;
        if (dir == 0) { be = bg; en = e; } else { be = 127 - e; en = 127 - bg; }
        s_wbeg[tid] = be;
        s_wend[tid] = valid ? en : -1;
    }
    __syncthreads();

    for (int t = 0; t < 128; ++t) {
        // early-issue Xg load for this rank's gate quarter
        float xg = (tid < 128) ? Xg[(size_t)t * 512 + rank * 128 + tid] : 0.f;

        // ---- gate GEMV quarter from smem: kg = k-half, c = column ----
        {
            int kg = tid >> 7, c = tid & 127;
            float acc = 0.f;
            const float* Wsp = Ws + kg * 64 * 128 + c;
            const float4* h4 = reinterpret_cast<const float4*>(h_cur) + kg * 16;
            #pragma unroll
            for (int j = 0; j < 16; ++j) {
                float4 hv = h4[j];
                acc = fmaf(hv.x, Wsp[(4 * j + 0) * 128], acc);
                acc = fmaf(hv.y, Wsp[(4 * j + 1) * 128], acc);
                acc = fmaf(hv.z, Wsp[(4 * j + 2) * 128], acc);
                acc = fmaf(hv.w, Wsp[(4 * j + 3) * 128], acc);
            }
            part[tid] = acc;
        }
        // word-event ballot (overlap with partials landing)
        if (tid < 64) {
            unsigned m = __ballot_sync(0xffffffffu, s_wend[tid] == t);
            if ((tid & 31) == 0) { if (tid < 32) s_m0 = m; else s_m1 = m; }
        }
        __syncthreads();
        if (tid < 128) {
            float g = part[tid] + part[128 + tid] + xg;
            int idx = (t & 1) * 512 + rank * 128 + tid;
            gates[idx] = g;
            unsigned la = smem_u32(&gates[idx]);
            #pragma unroll
            for (int p = 0; p < 4; ++p)
                if (p != rank) st_cluster_f32(la, p, g);
        }
        unsigned m0 = s_m0, m1 = s_m1;
        int wcnt = __popc(m0) + __popc(m1);
        cluster_sync_();

        // ---- word events ending at t ----
        if (wcnt) {
            if (tid < 128) { ew[tid] = 0.f; ewcw[tid] = 0.f; }
            while (m0 | m1) {
                int w;
                if (m0) { w = __ffs(m0) - 1; m0 &= m0 - 1; }
                else    { w = 32 + __ffs(m1) - 1; m1 &= m1 - 1; }
                int bg = s_wbeg[w];
                if (tid < 128) hb_s[tid] = hh[bg * 128 + tid];
                else           cb_s[tid - 128] = hc[bg * 128 + (tid - 128)];
                __syncthreads();
                // wvec slice GEMV (96 cols, 2-way k split over 192 threads)
                float wa = 0.f;
                if (tid < 192) {
                    int kg = (tid >= 96) ? 1 : 0;
                    int c = tid - kg * 96;
                    const float* Wp = Ww + kg * 64 * 96 + c;
                    const float4* h4 = reinterpret_cast<const float4*>(hb_s) + kg * 16;
                    #pragma unroll
                    for (int j = 0; j < 16; ++j) {
                        float4 hv = h4[j];
                        wa = fmaf(hv.x, Wp[(4 * j + 0) * 96], wa);
                        wa = fmaf(hv.y, Wp[(4 * j + 1) * 96], wa);
                        wa = fmaf(hv.z, Wp[(4 * j + 2) * 96], wa);
                        wa = fmaf(hv.w, Wp[(4 * j + 3) * 96], wa);
                    }
                }
                part[tid] = wa;
                __syncthreads();
                if (tid < 96) {
                    float v = part[tid] + part[96 + tid] + Wg[(size_t)w * 384 + rank * 96 + tid];
                    int idx = rank * 96 + tid;
                    wvec[idx] = v;
                    unsigned la = smem_u32(&wvec[idx]);
                    #pragma unroll
                    for (int p = 0; p < 4; ++p)
                        if (p != rank) st_cluster_f32(la, p, v);
                }
                cluster_sync_();
                if (tid < 128) {
                    float wi = sigm(wvec[tid]);
                    float wf = sigm(wvec[128 + tid]);
                    float wg = tanhf(wvec[256 + tid]);
                    cw[tid] = wf * cb_s[tid] + wi * wg;
                }
                __syncthreads();
                // lg slice GEMV (32 cols, 8-way k split)
                {
                    int c = tid & 31, kg = tid >> 5;
                    float a = 0.f;
                    const float* Wp = Wl + kg * 16 * 32 + c;
                    const float4* c4 = reinterpret_cast<const float4*>(cw) + kg * 4;
                    #pragma unroll
                    for (int j = 0; j < 4; ++j) {
                        float4 cv = c4[j];
                        a = fmaf(cv.x, Wp[(4 * j + 0) * 32], a);
                        a = fmaf(cv.y, Wp[(4 * j + 1) * 32], a);
                        a = fmaf(cv.z, Wp[(4 * j + 2) * 32], a);
                        a = fmaf(cv.w, Wp[(4 * j + 3) * 32], a);
                    }
                    part[tid] = a;
                }
                __syncthreads();
                if (tid < 32) {
                    float v = 0.f;
                    #pragma unroll
                    for (int j = 0; j < 8; ++j) v += part[j * 32 + tid];
                    v += Xl[(size_t)t * 128 + rank * 32 + tid];
                    int idx = rank * 32 + tid;
                    lvec[idx] = v;
                    unsigned la = smem_u32(&lvec[idx]);
                    #pragma unroll
                    for (int p = 0; p < 4; ++p)
                        if (p != rank) st_cluster_f32(la, p, v);
                }
                cluster_sync_();
                if (tid < 128) {
                    float e = expf(sigm(lvec[tid]));
                    ew[tid]   += e;
                    ewcw[tid] += e * cw[tid];
                }
                __syncthreads();
            }
        }

        // ---- pointwise combine (replicated in all ranks) ----
        if (tid < 128) {
            const float* G = gates + (t & 1) * 512;
            float i_ = sigm(G[tid]);
            float f_ = sigm(G[128 + tid]);
            float o_ = sigm(G[256 + tid]);
            float g_ = tanhf(G[384 + tid]);
            float cp = c_cur[tid], hp = h_cur[tid];
            float ct;
            if (wcnt) {
                float ec = expf(i_);
                ct = (ec * g_ + ewcw[tid]) / (ec + ew[tid]);
            } else {
                ct = f_ * cp + i_ * g_;
            }
            float ht = o_ * tanhf(ct);
            bool v = (dir == 0) ? (t < L) : (t >= 128 - L);
            float hn = v ? ht : hp;
            float cn = v ? ct : cp;
            h_cur[tid] = hn;
            c_cur[tid] = cn;
            hh[(t + 1) * 128 + tid] = hn;
            hc[(t + 1) * 128 + tid] = cn;
            if (rank == 0) {
                int pos = dir ? (127 - t) : t;
                g_feats[((size_t)b * 128 + pos) * 256 + dir * 128 + tid] = v ? ht : 0.f;
            }
        }
        __syncthreads();
    }
}

// ---------------- dense projection ----------------
__global__ void dense_kernel(const float* __restrict__ W, const float* __restrict__ bias)
{
    int row = blockIdx.x;
    int l = threadIdx.x;
    const float* f = g_feats + (size_t)row * 256;
    float acc = bias[l];
    #pragma unroll 8
    for (int j = 0; j < 256; ++j) acc = fmaf(f[j], W[j * 32 + l], acc);
    g_logits[(size_t)row * 32 + l] = acc;
}

// ---------------- CRF forward + gold, one warp per batch ----------------
__global__ void crf_kernel(const int* __restrict__ label, const int* __restrict__ seq_len,
                           const float* __restrict__ crf_T)
{
    int b = blockIdx.x, l = threadIdx.x;
    __shared__ float Ts[1024];
    for (int i = l; i < 1024; i += 32) Ts[i] = crf_T[i];
    __syncwarp();
    int L = seq_len[b];
    const float* lg = g_logits + (size_t)b * 128 * 32;
    float alpha = lg[l];
    for (int t = 1; t < 128; ++t) {
        float v[32];
        float vmax = -1e30f;
        #pragma unroll
        for (int i = 0; i < 32; ++i) {
            float ai = __shfl_sync(0xffffffffu, alpha, i);
            v[i] = ai + Ts[i * 32 + l];
            vmax = fmaxf(vmax, v[i]);
        }
        float s = 0.f;
        #pragma unroll
        for (int i = 0; i < 32; ++i) s += expf(v[i] - vmax);
        float nv = vmax + logf(s) + lg[t * 32 + l];
        if (t < L) alpha = nv;
    }
    float m = alpha;
    for (int o = 16; o; o >>= 1) m = fmaxf(m, __shfl_xor_sync(0xffffffffu, m, o));
    float e = expf(alpha - m);
    for (int o = 16; o; o >>= 1) e += __shfl_xor_sync(0xffffffffu, e, o);
    float logZ = m + logf(e);
    float gsum = 0.f;
    for (int t = l; t < 128; t += 32) {
        if (t < L) {
            int lab = label[b * 128 + t];
            gsum += lg[t * 32 + lab];
            if (t >= 1) gsum += Ts[label[b * 128 + t - 1] * 32 + lab];
        }
    }
    for (int o = 16; o; o >>= 1) gsum += __shfl_xor_sync(0xffffffffu, gsum, o);
    if (l == 0) g_res[b] = logZ - gsum;
}

__global__ void finalize_kernel(float* out)
{
    float s = 0.f;
    #pragma unroll
    for (int b = 0; b < 16; ++b) s += g_res[b];
    out[0] = s * 0.0625f;
}

// ---------------- launch ----------------
extern "C" void kernel_launch(void* const* d_in, const int* in_sizes, int n_in,
                              void* d_out, int out_size)
{
    const int*   char_ids    = (const int*)d_in[0];
    const int*   kb_word_ids = (const int*)d_in[1];
    const int*   word_begin  = (const int*)d_in[2];
    const int*   word_len    = (const int*)d_in[3];
    const int*   label       = (const int*)d_in[4];
    const int*   seq_len     = (const int*)d_in[5];
    const float* char_emb    = (const float*)d_in[6];
    const float* kb_emb      = (const float*)d_in[7];
    const float* dense_W     = (const float*)d_in[8];
    const float* dense_b     = (const float*)d_in[9];
    const float* crf_T       = (const float*)d_in[10];
    const float* f_Wcx = (const float*)d_in[11];
    const float* f_Wch = (const float*)d_in[12];
    const float* f_bc  = (const float*)d_in[13];
    const float* f_Wwx = (const float*)d_in[14];
    const float* f_Wwh = (const float*)d_in[15];
    const float* f_bw  = (const float*)d_in[16];
    const float* f_Wlx = (const float*)d_in[17];
    const float* f_Wlc = (const float*)d_in[18];
    const float* f_bl  = (const float*)d_in[19];
    const float* r_Wcx = (const float*)d_in[20];
    const float* r_Wch = (const float*)d_in[21];
    const float* r_bc  = (const float*)d_in[22];
    const float* r_Wwx = (const float*)d_in[23];
    const float* r_Wwh = (const float*)d_in[24];
    const float* r_bw  = (const float*)d_in[25];
    const float* r_Wlx = (const float*)d_in[26];
    const float* r_Wlc = (const float*)d_in[27];
    const float* r_bl  = (const float*)d_in[28];

    const int LAT_SMEM = LAT_SMEM_FLOATS * 4;  // 141824 B
    cudaFuncSetAttribute(lattice_kernel, cudaFuncAttributeMaxDynamicSharedMemorySize, LAT_SMEM);

    gemm_gather_kernel<<<dim3(8, 64), 256>>>(0, char_ids, kb_word_ids, char_emb, kb_emb,
                                             f_Wcx, r_Wcx, f_bc, r_bc, 512, 2048);
    gemm_gather_kernel<<<dim3(2, 64), 256>>>(1, char_ids, kb_word_ids, char_emb, kb_emb,
                                             f_Wlx, r_Wlx, f_bl, r_bl, 128, 2048);
    gemm_gather_kernel<<<dim3(6, 32), 256>>>(2, char_ids, kb_word_ids, char_emb, kb_emb,
                                             f_Wwx, r_Wwx, f_bw, r_bw, 384, 1024);

    lattice_kernel<<<128, 256, LAT_SMEM>>>(word_begin, word_len, seq_len,
                                           f_Wch, f_Wwh, f_Wlc, r_Wch, r_Wwh, r_Wlc);

    dense_kernel<<<2048, 32>>>(dense_W, dense_b);
    crf_kernel<<<16, 32>>>(label, seq_len, crf_T);
    finalize_kernel<<<1, 1>>>((float*)d_out);
}